// round 15
// baseline (speedup 1.0000x reference)
#include <cuda_runtime.h>
#include <cuda_fp16.h>
#include <cstdint>

#define EDIM   512
#define MROWS  32768
#define HDIM   1024
#define LN_EPS 1e-5f

// ---------------- mma.sync GEMM tiling (best measured config) ----------------
#define BM 128
#define BN 128
#define BK 64
#define NTHR 256

#define ROWB   144                   // 128B row + 16B pad: +4 banks/row, conflict-free ldmatrix
#define ARRB   (128 * ROWB)          // 18432
#define STAGEB (2 * ARRB)            // A, B -> 36864
#define NSTAGE 3
#define DYN_SMEM (NSTAGE * STAGEB)   // 110592  -> 2 CTAs/SM

#define MN (MROWS * EDIM)
#define MH (MROWS * HDIM)
#define WOFF_VO 0
#define WOFF_W1 262144
#define WOFF_W2 786432
#define WSTRIDE 1310720

// ---------------- device scratch ----------------
__device__ float   g_bvo[2 * EDIM];
__device__ float   g_zero[EDIM];            // zero bias for Wvo GEMM (static-zeroed)
__device__ __half  g_wh [2 * WSTRIDE];      // fp16 weights (B operands)
__device__ __half  g_woh[2 * EDIM * EDIM];  // fp16 Wo (A of Wvo GEMM)
__device__ __half  g_wvt[2 * EDIM * EDIM];  // fp16 Wv^T (B of Wvo GEMM)
__device__ __half  g_xh [2 * MN];           // fp16 inputs (GEMM-A operand + ln1 residual)
__device__ __half  g_x1h[2 * MN];           // fp16 x1 (GEMM operand + ln2 residual)
__device__ __half  g_hh [2l * MH];          // fp16 relu(FFN up)

// ---------------- PTX helpers ----------------
__device__ __forceinline__ uint32_t smem_u32(const void* p) {
    uint32_t a;
    asm("{ .reg .u64 t; cvta.to.shared.u64 t, %1; cvt.u32.u64 %0, t; }" : "=r"(a) : "l"(p));
    return a;
}
__device__ __forceinline__ void ldsm4(uint32_t* r, uint32_t addr) {
    asm volatile("ldmatrix.sync.aligned.x4.m8n8.shared.b16 {%0,%1,%2,%3}, [%4];"
                 : "=r"(r[0]), "=r"(r[1]), "=r"(r[2]), "=r"(r[3]) : "r"(addr));
}
__device__ __forceinline__ void mma_f16(float* c, const uint32_t* a, const uint32_t* b) {
    asm volatile(
        "mma.sync.aligned.m16n8k16.row.col.f32.f16.f16.f32 "
        "{%0,%1,%2,%3}, {%4,%5,%6,%7}, {%8,%9}, {%0,%1,%2,%3};"
        : "+f"(c[0]), "+f"(c[1]), "+f"(c[2]), "+f"(c[3])
        : "r"(a[0]), "r"(a[1]), "r"(a[2]), "r"(a[3]), "r"(b[0]), "r"(b[1]));
}
__device__ __forceinline__ void cp16(uint32_t dst, const void* src) {
    asm volatile("cp.async.cg.shared.global [%0], [%1], 16;" :: "r"(dst), "l"(src) : "memory");
}
__device__ __forceinline__ uint32_t mapa_rank(uint32_t saddr, uint32_t rank) {
    uint32_t r;
    asm("mapa.shared::cluster.u32 %0, %1, %2;" : "=r"(r) : "r"(saddr), "r"(rank));
    return r;
}
__device__ __forceinline__ float ld_dsmem(uint32_t addr) {
    float v;
    asm volatile("ld.shared::cluster.f32 %0, [%1];" : "=f"(v) : "r"(addr));
    return v;
}
#define CLUSTER_SYNC() do {                                            \
    asm volatile("barrier.cluster.arrive.aligned;" ::: "memory");      \
    asm volatile("barrier.cluster.wait.aligned;"   ::: "memory");      \
} while (0)

// ---------------------------------------------------------------------------
struct GArgs {
    const __half *Ah, *Bh;
    const float* bias;
    __half* Oh;
};

// Plain GEMM (used for Wvo prologue and FFN-up/relu): Oh = fp16(acc+bias[, relu])
template<int RELU>
__global__ __launch_bounds__(NTHR, 2)
void gemm_mma(GArgs ga0, GArgs ga1, int lda, int ldb, int K, int ldo)
{
    extern __shared__ char smraw[];
    const uint32_t sb = smem_u32(smraw);
    const GArgs ga = blockIdx.z ? ga1 : ga0;

    const int t  = threadIdx.x;
    const int l  = t & 31;
    const int w  = t >> 5;
    const int wr = w >> 2;
    const int wn = w & 3;
    const int ncol0 = blockIdx.x * BN;
    const int row0  = blockIdx.y * BM;

    const int crow = t >> 3;
    const int cc16 = (t & 7) * 16;
    const __half* pA = ga.Ah + (size_t)(row0 + crow) * lda + (t & 7) * 8;
    const __half* pB = ga.Bh + (size_t)(ncol0 + crow) * ldb + (t & 7) * 8;
    const uint32_t dbase = (uint32_t)crow * ROWB + cc16;

    float acc[4][4][4];
    #pragma unroll
    for (int mt = 0; mt < 4; mt++)
        #pragma unroll
        for (int nt = 0; nt < 4; nt++)
            #pragma unroll
            for (int e = 0; e < 4; e++) acc[mt][nt][e] = 0.f;

    const int nch = K / BK;

    auto fill = [&](int stage, int kt) {
        const uint32_t dst = sb + stage * STAGEB;
        #pragma unroll
        for (int j = 0; j < 4; j++) {
            cp16(dst + dbase + (uint32_t)(j * 32) * ROWB,        pA + (size_t)(j * 32) * lda + kt);
            cp16(dst + ARRB + dbase + (uint32_t)(j * 32) * ROWB, pB + (size_t)(j * 32) * ldb + kt);
        }
    };

    fill(0, 0);
    asm volatile("cp.async.commit_group;" ::: "memory");
    fill(1, BK);
    asm volatile("cp.async.commit_group;" ::: "memory");

    const uint32_t a_row  = (uint32_t)(wr * 64 + (l & 15)) * ROWB;
    const uint32_t a_chk  = (uint32_t)(l >> 4) << 4;
    const uint32_t b_row0 = (uint32_t)(wn * 32 + (l >> 4) * 8 + (l & 7)) * ROWB;
    const uint32_t b_chk  = (uint32_t)((l >> 3) & 1) << 4;

    auto compute_ks = [&](const uint32_t sA, int ks) {
        const uint32_t koff = (uint32_t)ks * 32;
        uint32_t b_h[2][4];
        #pragma unroll
        for (int p = 0; p < 2; p++)
            ldsm4(b_h[p], sA + ARRB + b_row0 + (uint32_t)(p * 16) * ROWB + koff + b_chk);
        uint32_t a[4][4];
        #pragma unroll
        for (int mt = 0; mt < 4; mt++)
            ldsm4(a[mt], sA + a_row + (uint32_t)(mt * 16) * ROWB + koff + a_chk);
        #pragma unroll
        for (int mt = 0; mt < 4; mt++)
            #pragma unroll
            for (int nt = 0; nt < 4; nt++)
                mma_f16(acc[mt][nt], a[mt], &b_h[nt >> 1][(nt & 1) * 2]);
    };

    int st_cur = 0, st_n2 = 2;
    for (int ch = 0; ch < nch; ch++) {
        asm volatile("cp.async.wait_group 1;" ::: "memory");
        __syncthreads();
        const uint32_t sA = sb + st_cur * STAGEB;
        compute_ks(sA, 0);
        if (ch + 2 < nch) fill(st_n2, (ch + 2) * BK);
        asm volatile("cp.async.commit_group;" ::: "memory");
        #pragma unroll
        for (int ks = 1; ks < 4; ks++) compute_ks(sA, ks);
        st_cur = (st_cur == 2) ? 0 : st_cur + 1;
        st_n2  = (st_n2  == 2) ? 0 : st_n2  + 1;
    }

    #pragma unroll
    for (int mt = 0; mt < 4; mt++) {
        #pragma unroll
        for (int nt = 0; nt < 4; nt++) {
            const int r_base = row0 + wr * 64 + mt * 16 + (l >> 2);
            const int gcol   = ncol0 + wn * 32 + nt * 8 + (l & 3) * 2;
            const float b0v = __ldg(ga.bias + gcol);
            const float b1v = __ldg(ga.bias + gcol + 1);
            #pragma unroll
            for (int h = 0; h < 2; h++) {
                float v0 = acc[mt][nt][h * 2 + 0] + b0v;
                float v1 = acc[mt][nt][h * 2 + 1] + b1v;
                if (RELU) { v0 = fmaxf(v0, 0.f); v1 = fmaxf(v1, 0.f); }
                const size_t ro = (size_t)(r_base + h * 8);
                *reinterpret_cast<__half2*>(ga.Oh + ro * ldo + gcol) = __floats2half2_rn(v0, v1);
            }
        }
    }
}

// ---------------------------------------------------------------------------
// Cluster-fused GEMM + residual + LayerNorm.
// Cluster (4,1,1) along N covers the full 512-wide row; per-row stats are
// reduced across ranks through DSMEM. LN operates on fp32 accumulators.
// MODE 0: x1h = fp16(LN(acc + bias + resh))       (ln1, after gemm A)
// MODE 1: out[row, coloff+col] = LN(...)  (fp32)  (ln2, after gemm C)
struct GLArgs {
    const __half *Ah, *Bh;
    const float* bias;
    const __half* resh;      // residual, ld = EDIM
    const float *lg, *lb;    // LN gamma/beta
    __half* oh;              // MODE 0 output (ld = EDIM)
    float* of;               // MODE 1 output (ld = 2*EDIM)
    int coloff;
};

template<int MODE>
__global__ __launch_bounds__(NTHR, 2) __cluster_dims__(4, 1, 1)
void gemm_ln(GLArgs ga0, GLArgs ga1, int lda, int ldb, int K)
{
    extern __shared__ char smraw[];
    const uint32_t sb = smem_u32(smraw);
    const GLArgs ga = blockIdx.z ? ga1 : ga0;

    const int t  = threadIdx.x;
    const int l  = t & 31;
    const int w  = t >> 5;
    const int wr = w >> 2;
    const int wn = w & 3;
    const int ncol0 = blockIdx.x * BN;       // blockIdx.x == cluster rank (0..3)
    const int row0  = blockIdx.y * BM;

    const int crow = t >> 3;
    const int cc16 = (t & 7) * 16;
    const __half* pA = ga.Ah + (size_t)(row0 + crow) * lda + (t & 7) * 8;
    const __half* pB = ga.Bh + (size_t)(ncol0 + crow) * ldb + (t & 7) * 8;
    const uint32_t dbase = (uint32_t)crow * ROWB + cc16;

    float acc[4][4][4];
    #pragma unroll
    for (int mt = 0; mt < 4; mt++)
        #pragma unroll
        for (int nt = 0; nt < 4; nt++)
            #pragma unroll
            for (int e = 0; e < 4; e++) acc[mt][nt][e] = 0.f;

    const int nch = K / BK;

    auto fill = [&](int stage, int kt) {
        const uint32_t dst = sb + stage * STAGEB;
        #pragma unroll
        for (int j = 0; j < 4; j++) {
            cp16(dst + dbase + (uint32_t)(j * 32) * ROWB,        pA + (size_t)(j * 32) * lda + kt);
            cp16(dst + ARRB + dbase + (uint32_t)(j * 32) * ROWB, pB + (size_t)(j * 32) * ldb + kt);
        }
    };

    fill(0, 0);
    asm volatile("cp.async.commit_group;" ::: "memory");
    fill(1, BK);
    asm volatile("cp.async.commit_group;" ::: "memory");

    const uint32_t a_row  = (uint32_t)(wr * 64 + (l & 15)) * ROWB;
    const uint32_t a_chk  = (uint32_t)(l >> 4) << 4;
    const uint32_t b_row0 = (uint32_t)(wn * 32 + (l >> 4) * 8 + (l & 7)) * ROWB;
    const uint32_t b_chk  = (uint32_t)((l >> 3) & 1) << 4;

    auto compute_ks = [&](const uint32_t sA, int ks) {
        const uint32_t koff = (uint32_t)ks * 32;
        uint32_t b_h[2][4];
        #pragma unroll
        for (int p = 0; p < 2; p++)
            ldsm4(b_h[p], sA + ARRB + b_row0 + (uint32_t)(p * 16) * ROWB + koff + b_chk);
        uint32_t a[4][4];
        #pragma unroll
        for (int mt = 0; mt < 4; mt++)
            ldsm4(a[mt], sA + a_row + (uint32_t)(mt * 16) * ROWB + koff + a_chk);
        #pragma unroll
        for (int mt = 0; mt < 4; mt++)
            #pragma unroll
            for (int nt = 0; nt < 4; nt++)
                mma_f16(acc[mt][nt], a[mt], &b_h[nt >> 1][(nt & 1) * 2]);
    };

    int st_cur = 0, st_n2 = 2;
    for (int ch = 0; ch < nch; ch++) {
        asm volatile("cp.async.wait_group 1;" ::: "memory");
        __syncthreads();
        const uint32_t sA = sb + st_cur * STAGEB;
        compute_ks(sA, 0);
        if (ch + 2 < nch) fill(st_n2, (ch + 2) * BK);
        asm volatile("cp.async.commit_group;" ::: "memory");
        #pragma unroll
        for (int ks = 1; ks < 4; ks++) compute_ks(sA, ks);
        st_cur = (st_cur == 2) ? 0 : st_cur + 1;
        st_n2  = (st_n2  == 2) ? 0 : st_n2  + 1;
    }

    // ---- fused residual + LN epilogue ----
    __syncthreads();                          // all warps done with stage smem
    float* rowsum = (float*)smraw;            // [128]
    float* rowsq  = rowsum + 128;             // [128]
    float* fmean  = rowsum + 256;             // [128]
    float* frstd  = rowsum + 384;             // [128]

    if (t < 128) { rowsum[t] = 0.f; rowsq[t] = 0.f; }
    __syncthreads();

    // bias + residual (into acc), per-row partial stats
    #pragma unroll
    for (int mt = 0; mt < 4; mt++) {
        #pragma unroll
        for (int h = 0; h < 2; h++) {
            const int rloc = wr * 64 + mt * 16 + (l >> 2) + h * 8;
            float s = 0.f, q = 0.f;
            #pragma unroll
            for (int nt = 0; nt < 4; nt++) {
                const int gcol = ncol0 + wn * 32 + nt * 8 + (l & 3) * 2;
                const __half2 rh = *reinterpret_cast<const __half2*>(
                    ga.resh + (size_t)(row0 + rloc) * EDIM + gcol);
                const float2 rf = __half22float2(rh);
                float v0 = acc[mt][nt][h * 2 + 0] + __ldg(ga.bias + gcol)     + rf.x;
                float v1 = acc[mt][nt][h * 2 + 1] + __ldg(ga.bias + gcol + 1) + rf.y;
                acc[mt][nt][h * 2 + 0] = v0;
                acc[mt][nt][h * 2 + 1] = v1;
                s += v0 + v1;
                q += v0 * v0 + v1 * v1;
            }
            // quad reduce (lanes sharing a row differ in l&3)
            s += __shfl_xor_sync(0xffffffffu, s, 1);
            s += __shfl_xor_sync(0xffffffffu, s, 2);
            q += __shfl_xor_sync(0xffffffffu, q, 1);
            q += __shfl_xor_sync(0xffffffffu, q, 2);
            if ((l & 3) == 0) {
                atomicAdd(&rowsum[rloc], s);
                atomicAdd(&rowsq[rloc], q);
            }
        }
    }
    __syncthreads();
    CLUSTER_SYNC();                           // all ranks' rowsum/rowsq ready

    if (t < 128) {
        const uint32_t myrank = (uint32_t)(blockIdx.x & 3);
        float s = rowsum[t], q = rowsq[t];
        #pragma unroll
        for (uint32_t r = 0; r < 4; r++) {
            if (r != myrank) {
                s += ld_dsmem(mapa_rank(sb + (uint32_t)t * 4, r));
                q += ld_dsmem(mapa_rank(sb + 512 + (uint32_t)t * 4, r));
            }
        }
        const float mean = s * (1.0f / 512.0f);
        const float var  = q * (1.0f / 512.0f) - mean * mean;
        fmean[t] = mean;
        frstd[t] = rsqrtf(var + LN_EPS);
    }
    CLUSTER_SYNC();                           // peers done reading; fmean visible

    #pragma unroll
    for (int mt = 0; mt < 4; mt++) {
        #pragma unroll
        for (int h = 0; h < 2; h++) {
            const int rloc = wr * 64 + mt * 16 + (l >> 2) + h * 8;
            const float mean = fmean[rloc];
            const float rstd = frstd[rloc];
            #pragma unroll
            for (int nt = 0; nt < 4; nt++) {
                const int gcol = ncol0 + wn * 32 + nt * 8 + (l & 3) * 2;
                const float o0 = (acc[mt][nt][h * 2 + 0] - mean) * rstd * __ldg(ga.lg + gcol)
                                 + __ldg(ga.lb + gcol);
                const float o1 = (acc[mt][nt][h * 2 + 1] - mean) * rstd * __ldg(ga.lg + gcol + 1)
                                 + __ldg(ga.lb + gcol + 1);
                const size_t ro = (size_t)(row0 + rloc);
                if (MODE == 0) {
                    *reinterpret_cast<__half2*>(ga.oh + ro * EDIM + gcol) =
                        __floats2half2_rn(o0, o1);
                } else {
                    *reinterpret_cast<float2*>(ga.of + ro * (2 * EDIM) + ga.coloff + gcol) =
                        make_float2(o0, o1);
                }
            }
        }
    }
}

// ---------------------------------------------------------------------------
__global__ void conv_in_kernel(const float* __restrict__ src0, const float* __restrict__ src1,
                               __half* __restrict__ h, int n4)
{
    const int i = blockIdx.x * blockDim.x + threadIdx.x;
    if (i >= n4) return;
    const float* src = blockIdx.z ? src1 : src0;
    const size_t base = (size_t)blockIdx.z * n4;
    const float4 v = reinterpret_cast<const float4*>(src)[i];
    const size_t o = (base + i) * 4;
    reinterpret_cast<__half2*>(h + o)[0] = __floats2half2_rn(v.x, v.y);
    reinterpret_cast<__half2*>(h + o)[1] = __floats2half2_rn(v.z, v.w);
}

struct ConvSet { const float* src; __half* dst; int n4; };
__global__ void conv_w_kernel(ConvSet s0, ConvSet s1, ConvSet s2,
                              ConvSet s3, ConvSet s4, ConvSet s5)
{
    ConvSet ss = s0;
    if (blockIdx.y == 1) ss = s1;
    else if (blockIdx.y == 2) ss = s2;
    else if (blockIdx.y == 3) ss = s3;
    else if (blockIdx.y == 4) ss = s4;
    else if (blockIdx.y == 5) ss = s5;
    const int i = blockIdx.x * blockDim.x + threadIdx.x;
    if (i >= ss.n4) return;
    const float4 v = reinterpret_cast<const float4*>(ss.src)[i];
    const size_t o = (size_t)i * 4;
    reinterpret_cast<__half2*>(ss.dst + o)[0] = __floats2half2_rn(v.x, v.y);
    reinterpret_cast<__half2*>(ss.dst + o)[1] = __floats2half2_rn(v.z, v.w);
}

// ---------------------------------------------------------------------------
struct TransArgs { const float *Wv, *Wo, *bv, *bo; __half* wvt; float* bvo; };
__global__ void trans_bvo_kernel(TransArgs t0, TransArgs t1)
{
    const TransArgs f = blockIdx.z ? t1 : t0;
    const int tx = threadIdx.x, ty = threadIdx.y;

    if (blockIdx.x == 16) {
        const int tid = ty * 32 + tx;
        if (tid < 256) {
            const int j0   = blockIdx.y * 32;
            const int warp = tid >> 5, lane = tid & 31;
            const int row  = j0 + warp * 4 + (lane >> 3);
            const int sub  = lane & 7;
            float s = 0.f;
            for (int k = sub; k < 512; k += 8) s += f.Wo[row * 512 + k] * f.bv[k];
            #pragma unroll
            for (int o = 4; o > 0; o >>= 1) s += __shfl_xor_sync(0xffffffffu, s, o);
            if (sub == 0) f.bvo[row] = s + f.bo[row];
        }
        return;
    }

    __shared__ float tile[32][33];
    const int k0 = blockIdx.y * 32;
    const int m0 = blockIdx.x * 32;
    tile[ty][tx] = f.Wv[(size_t)(k0 + ty) * 512 + m0 + tx];
    __syncthreads();
    f.wvt[(size_t)(m0 + ty) * 512 + k0 + tx] = __float2half_rn(tile[tx][ty]);
}

// ---------------------------------------------------------------------------
extern "C" void kernel_launch(void* const* d_in, const int* in_sizes, int n_in,
                              void* d_out, int out_size)
{
    const float* dna = (const float*)d_in[0];
    const float* mol = (const float*)d_in[1];
    const float* in_w[2]  = {(const float*)d_in[2],  (const float*)d_in[6]};
    const float* in_b[2]  = {(const float*)d_in[3],  (const float*)d_in[7]};
    const float* out_w[2] = {(const float*)d_in[4],  (const float*)d_in[8]};
    const float* out_b[2] = {(const float*)d_in[5],  (const float*)d_in[9]};
    const float* lnA_g[2] = {(const float*)d_in[10], (const float*)d_in[12]};
    const float* lnA_b[2] = {(const float*)d_in[11], (const float*)d_in[13]};
    const float* lnC_g[2] = {(const float*)d_in[14], (const float*)d_in[16]};
    const float* lnC_b[2] = {(const float*)d_in[15], (const float*)d_in[17]};
    const float* w1[2] = {(const float*)d_in[18], (const float*)d_in[22]};
    const float* b1[2] = {(const float*)d_in[19], (const float*)d_in[23]};
    const float* w2[2] = {(const float*)d_in[20], (const float*)d_in[24]};
    const float* b2[2] = {(const float*)d_in[21], (const float*)d_in[25]};
    float* out = (float*)d_out;

    float *bvo, *zero;
    __half *wh, *woh, *wvt, *xh, *x1h, *hh;
    cudaGetSymbolAddress((void**)&bvo,  g_bvo);
    cudaGetSymbolAddress((void**)&zero, g_zero);
    cudaGetSymbolAddress((void**)&wh,   g_wh);
    cudaGetSymbolAddress((void**)&woh,  g_woh);
    cudaGetSymbolAddress((void**)&wvt,  g_wvt);
    cudaGetSymbolAddress((void**)&xh,   g_xh);
    cudaGetSymbolAddress((void**)&x1h,  g_x1h);
    cudaGetSymbolAddress((void**)&hh,   g_hh);

    cudaFuncSetAttribute(gemm_mma<0>, cudaFuncAttributeMaxDynamicSharedMemorySize, DYN_SMEM);
    cudaFuncSetAttribute(gemm_mma<1>, cudaFuncAttributeMaxDynamicSharedMemorySize, DYN_SMEM);
    cudaFuncSetAttribute(gemm_ln<0>,  cudaFuncAttributeMaxDynamicSharedMemorySize, DYN_SMEM);
    cudaFuncSetAttribute(gemm_ln<1>,  cudaFuncAttributeMaxDynamicSharedMemorySize, DYN_SMEM);

    static cudaStream_t s2 = nullptr;
    static cudaEvent_t evFork = nullptr, evJoin = nullptr;
    if (s2 == nullptr) {
        cudaStreamCreateWithFlags(&s2, cudaStreamNonBlocking);
        cudaEventCreateWithFlags(&evFork, cudaEventDisableTiming);
        cudaEventCreateWithFlags(&evJoin, cudaEventDisableTiming);
    }

    // ---- prologue: weight path on s2, input conversion on main stream ----
    cudaEventRecord(evFork, 0);
    cudaStreamWaitEvent(s2, evFork, 0);

    {
        const int nW = HDIM * EDIM / 4;
        const int nO = EDIM * EDIM / 4;
        ConvSet c0 = {w1[0],    wh + 0 * WSTRIDE + WOFF_W1, nW};
        ConvSet c1 = {w2[0],    wh + 0 * WSTRIDE + WOFF_W2, nW};
        ConvSet c2 = {w1[1],    wh + 1 * WSTRIDE + WOFF_W1, nW};
        ConvSet c3 = {w2[1],    wh + 1 * WSTRIDE + WOFF_W2, nW};
        ConvSet c4 = {out_w[0], woh,                        nO};
        ConvSet c5 = {out_w[1], woh + EDIM * EDIM,          nO};
        conv_w_kernel<<<dim3(nW / 256, 6), 256, 0, s2>>>(c0, c1, c2, c3, c4, c5);

        TransArgs t0 = {in_w[0] + 2 * EDIM * EDIM, out_w[0], in_b[0] + 2 * EDIM, out_b[0],
                        wvt,               bvo + 0 * EDIM};
        TransArgs t1 = {in_w[1] + 2 * EDIM * EDIM, out_w[1], in_b[1] + 2 * EDIM, out_b[1],
                        wvt + EDIM * EDIM, bvo + 1 * EDIM};
        trans_bvo_kernel<<<dim3(17, 16, 2), dim3(32, 32), 0, s2>>>(t0, t1);

        GArgs a0 = {woh,               wvt,               zero, wh + 0 * WSTRIDE + WOFF_VO};
        GArgs a1 = {woh + EDIM * EDIM, wvt + EDIM * EDIM, zero, wh + 1 * WSTRIDE + WOFF_VO};
        gemm_mma<0><<<dim3(EDIM / BN, EDIM / BM, 2), NTHR, DYN_SMEM, s2>>>(
            a0, a1, EDIM, EDIM, EDIM, EDIM);
        cudaEventRecord(evJoin, s2);
    }

    conv_in_kernel<<<dim3(MN / 4 / 256, 1, 2), 256>>>(dna, mol, xh, MN / 4);
    cudaStreamWaitEvent(0, evJoin, 0);

    // ---- main pipeline (both problem streams via blockIdx.z) ----
    // stream 0 (dna side) attends over mol (xh+MN); stream 1 over dna (xh+0)
    // gemm A + ln1 (cluster-fused) -> x1h
    {
        GLArgs a0 = {xh + MN, wh + 0 * WSTRIDE + WOFF_VO, bvo + 0 * EDIM,
                     xh,      lnA_g[0], lnA_b[0], x1h,      nullptr, 0};
        GLArgs a1 = {xh,      wh + 1 * WSTRIDE + WOFF_VO, bvo + 1 * EDIM,
                     xh + MN, lnA_g[1], lnA_b[1], x1h + MN, nullptr, 0};
        gemm_ln<0><<<dim3(EDIM / BN, MROWS / BM, 2), NTHR, DYN_SMEM>>>(
            a0, a1, EDIM, EDIM, EDIM);
    }
    // gemm B (FFN up + relu) -> hh
    {
        GArgs a0 = {x1h,      wh + 0 * WSTRIDE + WOFF_W1, b1[0], hh};
        GArgs a1 = {x1h + MN, wh + 1 * WSTRIDE + WOFF_W1, b1[1], hh + MH};
        gemm_mma<1><<<dim3(HDIM / BN, MROWS / BM, 2), NTHR, DYN_SMEM>>>(
            a0, a1, EDIM, EDIM, EDIM, HDIM);
    }
    // gemm C + ln2 (cluster-fused) -> output halves
    {
        GLArgs a0 = {hh,      wh + 0 * WSTRIDE + WOFF_W2, b2[0],
                     x1h,      lnC_g[0], lnC_b[0], nullptr, out, 0};
        GLArgs a1 = {hh + MH, wh + 1 * WSTRIDE + WOFF_W2, b2[1],
                     x1h + MN, lnC_g[1], lnC_b[1], nullptr, out, EDIM};
        gemm_ln<1><<<dim3(EDIM / BN, MROWS / BM, 2), NTHR, DYN_SMEM>>>(
            a0, a1, HDIM, HDIM, HDIM);
    }
}